// round 12
// baseline (speedup 1.0000x reference)
#include <cuda_runtime.h>
#include <cstdint>

#define Bb 4096
#define Nn 256
#define Dd 64
#define Cc 3
#define Mm 32

#define OUT_XI_OFF ((size_t)Bb * Dd)
#define OUT_HJ_OFF (OUT_XI_OFF + (size_t)Bb * Cc)
#define OUT_XJ_OFF (OUT_HJ_OFF + (size_t)Bb * Nn * Dd)

// ---- dynamic smem layout (byte offsets) ----
#define SMO_A      0        // 256 x 64 fp32, chunk-rotated = 65536 (warp-private bands)
#define SMO_BF     65536    // B frags (tf32-rounded): 8kk x 4nt x 32 lanes x 8B = 8192
#define SMO_WH     73728    // 96 x 64 fp32 = 24576
#define SMO_XJ     98304    // 2 x 768 fp32 = 6144 (double buffered, warp-private slices)
#define SMO_HI     104448   // 2 x 64 fp32 = 512
#define SMO_BASEC  104960   // 32 x float4 = 512
#define SMO_MIP    105472   // 8 x 32 fp32 = 1024
#define SMO_XA     106496   // 8 x 4 fp32 = 128
#define SMO_MIF    106624   // 32 fp32 = 128
#define SMO_XIV    106752   // 2 x 4 fp32 = 32
#define SMEM_TOTAL 106784

__device__ __forceinline__ uint32_t smem_u32(const void* p) {
    uint32_t a;
    asm("{ .reg .u64 t; cvta.to.shared.u64 t, %1; cvt.u32.u64 %0, t; }" : "=r"(a) : "l"(p));
    return a;
}
__device__ __forceinline__ float silu_f(float x) {
    float e, r;
    asm("ex2.approx.f32 %0, %1;" : "=f"(e) : "f"(x * -1.442695041f));
    asm("rcp.approx.f32 %0, %1;" : "=f"(r) : "f"(e + 1.0f));
    return x * r;
}
__device__ __forceinline__ uint32_t to_tf32(float f) {
    uint32_t u;
    asm("cvt.rna.tf32.f32 %0, %1;" : "=r"(u) : "f"(f));
    return u;
}
__device__ __forceinline__ void mma_tf32(float* c, uint32_t a0, uint32_t a1,
                                         uint32_t a2, uint32_t a3,
                                         uint32_t b0, uint32_t b1) {
    asm volatile(
        "mma.sync.aligned.m16n8k8.row.col.f32.tf32.tf32.f32 "
        "{%0,%1,%2,%3}, {%4,%5,%6,%7}, {%8,%9}, {%0,%1,%2,%3};"
        : "+f"(c[0]), "+f"(c[1]), "+f"(c[2]), "+f"(c[3])
        : "r"(a0), "r"(a1), "r"(a2), "r"(a3), "r"(b0), "r"(b1));
}
#define CP16(dst, src) asm volatile("cp.async.cg.shared.global [%0], [%1], 16;" :: "r"(dst), "l"(src))
#define CP4(dst, src)  asm volatile("cp.async.ca.shared.global [%0], [%1], 4;"  :: "r"(dst), "l"(src))
#define CPCOMMIT()     asm volatile("cp.async.commit_group;" ::: "memory")
#define CPWAIT0()      asm volatile("cp.async.wait_group 0;" ::: "memory")

__global__ __launch_bounds__(256, 2) void e2gn2_kernel(
    const float* __restrict__ hi, const float* __restrict__ xi,
    const float* __restrict__ hj, const float* __restrict__ xj,
    const float* __restrict__ We, const float* __restrict__ be,
    const float* __restrict__ Wx, const float* __restrict__ bx,
    const float* __restrict__ Wx2, const float* __restrict__ bx2,
    const float* __restrict__ Wh, const float* __restrict__ bh,
    float* __restrict__ out)
{
    extern __shared__ char sm[];

    const int tid  = threadIdx.x;
    const int w    = tid >> 5;
    const int lane = tid & 31;
    const int q    = lane >> 2;   // groupID (row in frag)
    const int s    = lane & 3;    // threadID_in_group

    float*  smWh   = (float*)(sm + SMO_WH);
    float*  smXjF  = (float*)(sm + SMO_XJ);
    float*  smHiF  = (float*)(sm + SMO_HI);
    float4* smBaseC= (float4*)(sm + SMO_BASEC);
    float*  smMip  = (float*)(sm + SMO_MIP);
    float*  smXa   = (float*)(sm + SMO_XA);
    float*  smMif  = (float*)(sm + SMO_MIF);
    float*  smXiV  = (float*)(sm + SMO_XIV);

    const uint32_t smBase = smem_u32(sm);

    // ================= one-time init =================
    for (int i = tid; i < 6144; i += 256) smWh[i] = Wh[i];
    // B frags (RNA-rounded tf32): thread holds b0=(k=kk*8+t, n=nt*8+g), b1=(k+4, n)
    for (int idx = tid; idx < 8 * 4 * 32; idx += 256) {
        const int kk = idx >> 7, rest = idx & 127;
        const int nt = rest >> 5, l2 = rest & 31;
        const int t2 = l2 & 3, g2 = l2 >> 2;
        const int k0 = kk * 8 + t2, n = nt * 8 + g2;
        uint2 bfr;
        bfr.x = to_tf32(We[(Dd + k0)     * Mm + n]);
        bfr.y = to_tf32(We[(Dd + k0 + 4) * Mm + n]);
        *(uint2*)(sm + SMO_BF + ((kk * 4 + nt) * 32 + l2) * 8) = bfr;
    }
    float wxr_[8];
    #pragma unroll
    for (int nt = 0; nt < 4; nt++) {
        wxr_[nt * 2 + 0] = Wx[nt * 8 + 2 * s + 0];
        wxr_[nt * 2 + 1] = Wx[nt * 8 + 2 * s + 1];
    }
    const float bxv  = bx[0];
    const float bx2v = bx2[0];
    __syncthreads();   // BF/WH visible before any MMA/tail

    const int bstart = blockIdx.x, bstride = gridDim.x;
    int p = 0;

    // ---- per-warp staging: warp w's A band + xj slice (+ w2: hi, xiv) ----
    #define STAGE_WARP(bsrc, pb) do {                                              \
        const float* hjb_ = hj + (size_t)(bsrc) * Nn * Dd;                         \
        _Pragma("unroll")                                                          \
        for (int j = 0; j < 16; j++) {                                             \
            const int row_ = w * 32 + j * 2 + (lane >> 4);                         \
            const int ch_  = lane & 15;                                            \
            CP16(smBase + SMO_A + row_ * 256 + (((ch_ + row_) & 15) << 4),         \
                 hjb_ + row_ * 64 + ch_ * 4);                                      \
        }                                                                          \
        if (lane < 24) CP16(smBase + SMO_XJ + (pb) * 3072 + w * 384 + lane * 16,   \
                            xj + (size_t)(bsrc) * 768 + w * 96 + lane * 4);        \
        if (w == 2) {                                                              \
            if (lane < 16) CP16(smBase + SMO_HI + (pb) * 256 + lane * 16,          \
                                hi + (size_t)(bsrc) * 64 + lane * 4);              \
            else if (lane < 19) CP4(smBase + SMO_XIV + (pb) * 16 + (lane-16) * 4,  \
                                    xi + (size_t)(bsrc) * 3 + (lane - 16));        \
        }                                                                          \
        CPCOMMIT();                                                                \
    } while (0)

    STAGE_WARP(bstart, 0);   // prologue

    // ldmatrix per-lane row constants: lane supplies row rL = w*32 + mt*16 + (lane&15),
    // chunk base lg = lane>>4 (0: chunk 2kk, 1: chunk 2kk+1), rotation (chunk + row)&15
    const int rl16 = lane & 15;
    const int lg   = lane >> 4;

    // ================= persistent pipelined loop =================
    for (int b = bstart; b < Bb; b += bstride) {
        const int  bn = b + bstride;
        const bool hn = bn < Bb;

        CPWAIT0();   // per-warp: only THIS warp's band + slice must have landed

        // ---- hj + xj pass-through STG from smem (own band / slice) ----
        {
            float4* o4 = (float4*)(out + OUT_HJ_OFF + (size_t)b * Nn * Dd);
            #pragma unroll
            for (int j = 0; j < 16; j++) {
                const int row = w * 32 + j * 2 + (lane >> 4);
                const int ch  = lane & 15;
                o4[row * 16 + ch] = *(const float4*)(sm + SMO_A + row * 256 +
                                                     (((ch + row) & 15) << 4));
            }
            if (lane < 24) {
                float4* oxj = (float4*)(out + OUT_XJ_OFF + (size_t)b * 768);
                oxj[w * 24 + lane] =
                    *(const float4*)(sm + SMO_XJ + p * 3072 + w * 384 + lane * 16);
            }
        }

        // ---- MMA: own band rows [w*32, w*32+32); A via ldmatrix, raw-bits tf32 ----
        float acc[2][4][4];
        #pragma unroll
        for (int mt = 0; mt < 2; mt++)
            #pragma unroll
            for (int nt = 0; nt < 4; nt++)
                #pragma unroll
                for (int j = 0; j < 4; j++) acc[mt][nt][j] = 0.0f;

        #pragma unroll
        for (int mt = 0; mt < 2; mt++) {
            const int rL = w * 32 + mt * 16 + rl16;          // this lane's matrix row
            const uint32_t rowAddr = smBase + SMO_A + rL * 256;
            const int rotb = rL + lg;                         // chunk rotation base
            #pragma unroll
            for (int kk = 0; kk < 8; kk++) {
                uint32_t a0, a1, a2, a3;
                const uint32_t maddr = rowAddr + (((2 * kk + rotb) & 15) << 4);
                asm volatile(
                    "ldmatrix.sync.aligned.m8n8.x4.shared.b16 {%0,%1,%2,%3}, [%4];"
                    : "=r"(a0), "=r"(a1), "=r"(a2), "=r"(a3) : "r"(maddr));
                // a0..a3 are raw fp32 bits; MMA reads bits[31:13] -> RZ tf32
                #pragma unroll
                for (int nt = 0; nt < 4; nt++) {
                    const uint2 bf = *(const uint2*)(sm + SMO_BF +
                                        ((kk * 4 + nt) * 32 + lane) * 8);
                    mma_tf32(acc[mt][nt], a0, a1, a2, a3, bf.x, bf.y);
                }
            }
        }

        // warp 2: base[m] + {base, wu0, wu1, wu2}  (hi/xiv were its own loads)
        if (w == 2) {
            float s0 = __ldg(&be[lane]), s1 = 0.f, s2 = 0.f, s3 = 0.f;
            #pragma unroll
            for (int d = 0; d < Dd; d += 4) {
                s0 += smHiF[p * 64 + d + 0] * __ldg(&We[(d + 0) * Mm + lane]);
                s1 += smHiF[p * 64 + d + 1] * __ldg(&We[(d + 1) * Mm + lane]);
                s2 += smHiF[p * 64 + d + 2] * __ldg(&We[(d + 2) * Mm + lane]);
                s3 += smHiF[p * 64 + d + 3] * __ldg(&We[(d + 3) * Mm + lane]);
            }
            smBaseC[lane] = make_float4((s0 + s1) + (s2 + s3),
                                        __ldg(&We[(2 * Dd + 0) * Mm + lane]),
                                        __ldg(&We[(2 * Dd + 1) * Mm + lane]),
                                        __ldg(&We[(2 * Dd + 2) * Mm + lane]));
        }

        // ---- own A band consumed: issue next block's stage immediately ----
        if (hn) STAGE_WARP(bn, p ^ 1);
        else    CPCOMMIT();   // keep group count consistent

        __syncthreads();   // barrier(1): BaseC/xiv visible; gates smMip reuse

        // ---- epilogue ----
        const float xiv0 = smXiV[p * 4 + 0], xiv1 = smXiV[p * 4 + 1], xiv2 = smXiV[p * 4 + 2];
        const float* xjp = smXjF + p * 768;
        float u0_[4], u1_[4], u2_[4], q0_[4], q1_[4], q2_[4];
        #pragma unroll
        for (int mh = 0; mh < 4; mh++) {
            const int n = w * 32 + (mh >> 1) * 16 + (mh & 1) * 8 + q;
            u0_[mh] = xiv0 - xjp[n * 3 + 0];
            u1_[mh] = xiv1 - xjp[n * 3 + 1];
            u2_[mh] = xiv2 - xjp[n * 3 + 2];
            q0_[mh] = u0_[mh] * u0_[mh];
            q1_[mh] = u1_[mh] * u1_[mh];
            q2_[mh] = u2_[mh] * u2_[mh];
        }
        float micol[8];
        #pragma unroll
        for (int j = 0; j < 8; j++) micol[j] = 0.0f;
        float pr[4] = {0.f, 0.f, 0.f, 0.f};

        #pragma unroll
        for (int nt = 0; nt < 4; nt++) {
            const int col = nt * 8 + 2 * s;
            const float4 b0 = smBaseC[col];
            const float4 b1 = smBaseC[col + 1];
            #pragma unroll
            for (int mh = 0; mh < 4; mh++) {
                const int mt = mh >> 1, hf = mh & 1;
                float va = acc[mt][nt][hf * 2 + 0] + b0.x + q0_[mh] * b0.y
                         + q1_[mh] * b0.z + q2_[mh] * b0.w;
                float vb = acc[mt][nt][hf * 2 + 1] + b1.x + q0_[mh] * b1.y
                         + q1_[mh] * b1.z + q2_[mh] * b1.w;
                const float mv0 = silu_f(va);
                const float mv1 = silu_f(vb);
                micol[nt * 2 + 0] += mv0;
                micol[nt * 2 + 1] += mv1;
                pr[mh] += mv0 * wxr_[nt * 2 + 0] + mv1 * wxr_[nt * 2 + 1];
            }
        }
        float xa0 = 0.f, xa1 = 0.f, xa2 = 0.f;
        #pragma unroll
        for (int mh = 0; mh < 4; mh++) {
            float prr = pr[mh];
            prr += __shfl_xor_sync(0xffffffffu, prr, 1);
            prr += __shfl_xor_sync(0xffffffffu, prr, 2);
            const float px = silu_f(prr + bxv);
            xa0 += u0_[mh] * px; xa1 += u1_[mh] * px; xa2 += u2_[mh] * px;  // 4x per quad
        }
        #pragma unroll
        for (int j = 0; j < 8; j++) {
            micol[j] += __shfl_xor_sync(0xffffffffu, micol[j], 4);
            micol[j] += __shfl_xor_sync(0xffffffffu, micol[j], 8);
            micol[j] += __shfl_xor_sync(0xffffffffu, micol[j], 16);
        }
        if (lane < 4) {
            #pragma unroll
            for (int nt = 0; nt < 4; nt++) {
                smMip[w * 32 + nt * 8 + 2 * lane + 0] = micol[nt * 2 + 0];
                smMip[w * 32 + nt * 8 + 2 * lane + 1] = micol[nt * 2 + 1];
            }
        }
        #pragma unroll
        for (int off = 16; off; off >>= 1) {
            xa0 += __shfl_xor_sync(0xffffffffu, xa0, off);
            xa1 += __shfl_xor_sync(0xffffffffu, xa1, off);
            xa2 += __shfl_xor_sync(0xffffffffu, xa2, off);
        }
        if (lane == 0) { smXa[w*4+0] = xa0; smXa[w*4+1] = xa1; smXa[w*4+2] = xa2; }

        // ---- barrier(2): split — warps 2-7 arrive and RUN AHEAD; w0/w1 sync ----
        if (w < 2) {
            asm volatile("bar.sync 2, 256;" ::: "memory");
        } else {
            asm volatile("bar.arrive 2, 256;" ::: "memory");
        }

        // ---- tail (w0/w1 only; warps 2-7 already in next iteration) ----
        if (w == 0) {
            float mt = 0.0f;
            #pragma unroll
            for (int wi = 0; wi < 8; wi++) mt += smMip[wi * 32 + lane];
            smMif[lane] = mt;
            float v2 = mt * __ldg(&Wx2[lane]);
            #pragma unroll
            for (int off = 16; off; off >>= 1)
                v2 += __shfl_xor_sync(0xffffffffu, v2, off);
            const float phi2 = silu_f(v2 + bx2v);
            if (lane < Cc) {
                float xt = 0.0f;
                #pragma unroll
                for (int wi = 0; wi < 8; wi++) xt += smXa[wi * 4 + lane];
                out[OUT_XI_OFF + (size_t)b * Cc + lane] =
                    smXiV[p * 4 + lane] * phi2 + xt * (1.0f / (4.0f * (float)Nn));
            }
        }
        if (w < 2) {
            asm volatile("bar.sync 1, 64;" ::: "memory");   // smMif ready
            float a = __ldg(&bh[tid]);
            #pragma unroll 8
            for (int d = 0; d < Dd; d++)  a += smHiF[p * 64 + d] * smWh[d * Dd + tid];
            #pragma unroll 8
            for (int m = 0; m < Mm; m++)  a += smMif[m] * smWh[(Dd + m) * Dd + tid];
            out[(size_t)b * Dd + tid] = silu_f(a);
        }
        p ^= 1;
    }
    #undef STAGE_WARP
}

extern "C" void kernel_launch(void* const* d_in, const int* in_sizes, int n_in,
                              void* d_out, int out_size) {
    const float* hi  = (const float*)d_in[0];
    const float* xi  = (const float*)d_in[1];
    const float* hj  = (const float*)d_in[2];
    const float* xj  = (const float*)d_in[3];
    const float* We  = (const float*)d_in[4];
    const float* be  = (const float*)d_in[5];
    const float* Wx  = (const float*)d_in[6];
    const float* bx  = (const float*)d_in[7];
    const float* Wx2 = (const float*)d_in[8];
    const float* bx2 = (const float*)d_in[9];
    const float* Wh  = (const float*)d_in[10];
    const float* bh  = (const float*)d_in[11];
    float* out = (float*)d_out;

    cudaFuncSetAttribute(e2gn2_kernel,
                         cudaFuncAttributeMaxDynamicSharedMemorySize, SMEM_TOTAL);
    int smCount = 148;
    cudaDeviceGetAttribute(&smCount, cudaDevAttrMultiProcessorCount, 0);
    const int grid = 2 * smCount;

    e2gn2_kernel<<<grid, 256, SMEM_TOTAL>>>(hi, xi, hj, xj, We, be, Wx, bx,
                                            Wx2, bx2, Wh, bh, out);
}

// round 13
// speedup vs baseline: 1.0472x; 1.0472x over previous
#include <cuda_runtime.h>
#include <cstdint>

#define Bb 4096
#define Nn 256
#define Dd 64
#define Cc 3
#define Mm 32

#define OUT_XI_OFF ((size_t)Bb * Dd)
#define OUT_HJ_OFF (OUT_XI_OFF + (size_t)Bb * Cc)
#define OUT_XJ_OFF (OUT_HJ_OFF + (size_t)Bb * Nn * Dd)

// ---- dynamic smem layout (byte offsets) ----
#define SMO_A      0        // 256 x 64 fp32, chunk-rotated = 65536 (warp-private bands)
#define SMO_BF     65536    // B frags (tf32-rounded): 8kk x 4nt x 32 lanes x 8B = 8192
#define SMO_WH     73728    // 96 x 64 fp32 = 24576
#define SMO_XJ     98304    // 2 x 768 fp32 = 6144 (double buffered, warp-private slices)
#define SMO_HI     104448   // 2 x 64 fp32 = 512
#define SMO_BASEC  104960   // 32 x float4 = 512
#define SMO_MIP    105472   // 8 x 32 fp32 = 1024
#define SMO_XA     106496   // 8 x 4 fp32 = 128
#define SMO_MIF    106624   // 32 fp32 = 128
#define SMO_XIV    106752   // 2 x 4 fp32 = 32
#define SMEM_TOTAL 106784

__device__ __forceinline__ uint32_t smem_u32(const void* p) {
    uint32_t a;
    asm("{ .reg .u64 t; cvta.to.shared.u64 t, %1; cvt.u32.u64 %0, t; }" : "=r"(a) : "l"(p));
    return a;
}
__device__ __forceinline__ float silu_f(float x) {
    float e, r;
    asm("ex2.approx.f32 %0, %1;" : "=f"(e) : "f"(x * -1.442695041f));
    asm("rcp.approx.f32 %0, %1;" : "=f"(r) : "f"(e + 1.0f));
    return x * r;
}
__device__ __forceinline__ uint32_t to_tf32(float f) {
    uint32_t u;
    asm("cvt.rna.tf32.f32 %0, %1;" : "=r"(u) : "f"(f));
    return u;
}
__device__ __forceinline__ void mma_tf32(float* c, uint32_t a0, uint32_t a1,
                                         uint32_t a2, uint32_t a3,
                                         uint32_t b0, uint32_t b1) {
    asm volatile(
        "mma.sync.aligned.m16n8k8.row.col.f32.tf32.tf32.f32 "
        "{%0,%1,%2,%3}, {%4,%5,%6,%7}, {%8,%9}, {%0,%1,%2,%3};"
        : "+f"(c[0]), "+f"(c[1]), "+f"(c[2]), "+f"(c[3])
        : "r"(a0), "r"(a1), "r"(a2), "r"(a3), "r"(b0), "r"(b1));
}
__device__ __forceinline__ void stcs4(float* p, float4 v) {
    asm volatile("st.global.cs.v4.f32 [%0], {%1,%2,%3,%4};"
                 :: "l"(p), "f"(v.x), "f"(v.y), "f"(v.z), "f"(v.w) : "memory");
}
#define CP16(dst, src) asm volatile("cp.async.cg.shared.global [%0], [%1], 16;" :: "r"(dst), "l"(src))
#define CP4(dst, src)  asm volatile("cp.async.ca.shared.global [%0], [%1], 4;"  :: "r"(dst), "l"(src))
#define CPCOMMIT()     asm volatile("cp.async.commit_group;" ::: "memory")
#define CPWAIT0()      asm volatile("cp.async.wait_group 0;" ::: "memory")

__global__ __launch_bounds__(256, 2) void e2gn2_kernel(
    const float* __restrict__ hi, const float* __restrict__ xi,
    const float* __restrict__ hj, const float* __restrict__ xj,
    const float* __restrict__ We, const float* __restrict__ be,
    const float* __restrict__ Wx, const float* __restrict__ bx,
    const float* __restrict__ Wx2, const float* __restrict__ bx2,
    const float* __restrict__ Wh, const float* __restrict__ bh,
    float* __restrict__ out)
{
    extern __shared__ char sm[];

    const int tid  = threadIdx.x;
    const int w    = tid >> 5;
    const int lane = tid & 31;
    const int q    = lane >> 2;   // groupID (row in frag)
    const int s    = lane & 3;    // threadID_in_group

    float*  smWh   = (float*)(sm + SMO_WH);
    float*  smXjF  = (float*)(sm + SMO_XJ);
    float*  smHiF  = (float*)(sm + SMO_HI);
    float4* smBaseC= (float4*)(sm + SMO_BASEC);
    float*  smMip  = (float*)(sm + SMO_MIP);
    float*  smXa   = (float*)(sm + SMO_XA);
    float*  smMif  = (float*)(sm + SMO_MIF);
    float*  smXiV  = (float*)(sm + SMO_XIV);

    const uint32_t smBase = smem_u32(sm);

    // ================= one-time init =================
    for (int i = tid; i < 6144; i += 256) smWh[i] = Wh[i];
    // B frags (RNA-rounded tf32): thread holds b0=(k=kk*8+t, n=nt*8+g), b1=(k+4, n)
    for (int idx = tid; idx < 8 * 4 * 32; idx += 256) {
        const int kk = idx >> 7, rest = idx & 127;
        const int nt = rest >> 5, l2 = rest & 31;
        const int t2 = l2 & 3, g2 = l2 >> 2;
        const int k0 = kk * 8 + t2, n = nt * 8 + g2;
        uint2 bfr;
        bfr.x = to_tf32(We[(Dd + k0)     * Mm + n]);
        bfr.y = to_tf32(We[(Dd + k0 + 4) * Mm + n]);
        *(uint2*)(sm + SMO_BF + ((kk * 4 + nt) * 32 + l2) * 8) = bfr;
    }
    float wxr_[8];
    #pragma unroll
    for (int nt = 0; nt < 4; nt++) {
        wxr_[nt * 2 + 0] = Wx[nt * 8 + 2 * s + 0];
        wxr_[nt * 2 + 1] = Wx[nt * 8 + 2 * s + 1];
    }
    const float bxv  = bx[0];
    const float bx2v = bx2[0];
    __syncthreads();   // BF/WH visible before any MMA/tail

    const int bstart = blockIdx.x, bstride = gridDim.x;
    int p = 0;

    // ---- per-warp staging: warp w's A band + xj slice (+ w2: hi, xiv) ----
    #define STAGE_WARP(bsrc, pb) do {                                              \
        const float* hjb_ = hj + (size_t)(bsrc) * Nn * Dd;                         \
        _Pragma("unroll")                                                          \
        for (int j = 0; j < 16; j++) {                                             \
            const int row_ = w * 32 + j * 2 + (lane >> 4);                         \
            const int ch_  = lane & 15;                                            \
            CP16(smBase + SMO_A + row_ * 256 + (((ch_ + row_) & 15) << 4),         \
                 hjb_ + row_ * 64 + ch_ * 4);                                      \
        }                                                                          \
        if (lane < 24) CP16(smBase + SMO_XJ + (pb) * 3072 + w * 384 + lane * 16,   \
                            xj + (size_t)(bsrc) * 768 + w * 96 + lane * 4);        \
        if (w == 2) {                                                              \
            if (lane < 16) CP16(smBase + SMO_HI + (pb) * 256 + lane * 16,          \
                                hi + (size_t)(bsrc) * 64 + lane * 4);              \
            else if (lane < 19) CP4(smBase + SMO_XIV + (pb) * 16 + (lane-16) * 4,  \
                                    xi + (size_t)(bsrc) * 3 + (lane - 16));        \
        }                                                                          \
        CPCOMMIT();                                                                \
    } while (0)

    STAGE_WARP(bstart, 0);   // prologue

    // ================= persistent pipelined loop =================
    for (int b = bstart; b < Bb; b += bstride) {
        const int  bn = b + bstride;
        const bool hn = bn < Bb;

        CPWAIT0();   // per-warp: only THIS warp's band + slice must have landed

        // ---- hj + xj pass-through STG from smem (own band / slice), evict-first ----
        {
            float4* o4 = (float4*)(out + OUT_HJ_OFF + (size_t)b * Nn * Dd);
            #pragma unroll
            for (int j = 0; j < 16; j++) {
                const int row = w * 32 + j * 2 + (lane >> 4);
                const int ch  = lane & 15;
                stcs4(&((float*)(o4 + row * 16 + ch))[0],
                      *(const float4*)(sm + SMO_A + row * 256 + (((ch + row) & 15) << 4)));
            }
            if (lane < 24) {
                float4* oxj = (float4*)(out + OUT_XJ_OFF + (size_t)b * 768);
                stcs4(&((float*)(oxj + w * 24 + lane))[0],
                      *(const float4*)(sm + SMO_XJ + p * 3072 + w * 384 + lane * 16));
            }
        }

        // ---- MMA: own band rows [w*32, w*32+32), single-pass RNA tf32 ----
        float acc[2][4][4];
        #pragma unroll
        for (int mt = 0; mt < 2; mt++)
            #pragma unroll
            for (int nt = 0; nt < 4; nt++)
                #pragma unroll
                for (int j = 0; j < 4; j++) acc[mt][nt][j] = 0.0f;

        #pragma unroll
        for (int mt = 0; mt < 2; mt++) {
            const int r0 = w * 32 + mt * 16 + q;
            #pragma unroll
            for (int kk = 0; kk < 8; kk++) {
                const int cA0 = (2 * kk +     q)     & 15;
                const int cA2 = (2 * kk + 1 + q)     & 15;
                const int cB0 = (2 * kk +     q + 8) & 15;
                const int cB2 = (2 * kk + 1 + q + 8) & 15;
                const float fa0 = *(const float*)(sm + SMO_A + r0 * 256       + cA0 * 16 + s * 4);
                const float fa1 = *(const float*)(sm + SMO_A + (r0 + 8) * 256 + cB0 * 16 + s * 4);
                const float fa2 = *(const float*)(sm + SMO_A + r0 * 256       + cA2 * 16 + s * 4);
                const float fa3 = *(const float*)(sm + SMO_A + (r0 + 8) * 256 + cB2 * 16 + s * 4);
                const uint32_t a0 = to_tf32(fa0);
                const uint32_t a1 = to_tf32(fa1);
                const uint32_t a2 = to_tf32(fa2);
                const uint32_t a3 = to_tf32(fa3);
                #pragma unroll
                for (int nt = 0; nt < 4; nt++) {
                    const uint2 bf = *(const uint2*)(sm + SMO_BF +
                                        ((kk * 4 + nt) * 32 + lane) * 8);
                    mma_tf32(acc[mt][nt], a0, a1, a2, a3, bf.x, bf.y);
                }
            }
        }

        // warp 2: base[m] + {base, wu0, wu1, wu2}  (hi/xiv were its own loads)
        if (w == 2) {
            float s0 = __ldg(&be[lane]), s1 = 0.f, s2 = 0.f, s3 = 0.f;
            #pragma unroll
            for (int d = 0; d < Dd; d += 4) {
                s0 += smHiF[p * 64 + d + 0] * __ldg(&We[(d + 0) * Mm + lane]);
                s1 += smHiF[p * 64 + d + 1] * __ldg(&We[(d + 1) * Mm + lane]);
                s2 += smHiF[p * 64 + d + 2] * __ldg(&We[(d + 2) * Mm + lane]);
                s3 += smHiF[p * 64 + d + 3] * __ldg(&We[(d + 3) * Mm + lane]);
            }
            smBaseC[lane] = make_float4((s0 + s1) + (s2 + s3),
                                        __ldg(&We[(2 * Dd + 0) * Mm + lane]),
                                        __ldg(&We[(2 * Dd + 1) * Mm + lane]),
                                        __ldg(&We[(2 * Dd + 2) * Mm + lane]));
        }

        // ---- own A band consumed: issue next block's stage immediately ----
        if (hn) STAGE_WARP(bn, p ^ 1);
        else    CPCOMMIT();   // keep group count consistent

        __syncthreads();   // barrier(1): BaseC/xiv visible; gates smMip reuse

        // ---- epilogue (q arrays only; u recomputed at xa time) ----
        const float xiv0 = smXiV[p * 4 + 0], xiv1 = smXiV[p * 4 + 1], xiv2 = smXiV[p * 4 + 2];
        const float* xjp = smXjF + p * 768;
        float q0_[4], q1_[4], q2_[4];
        #pragma unroll
        for (int mh = 0; mh < 4; mh++) {
            const int n = w * 32 + (mh >> 1) * 16 + (mh & 1) * 8 + q;
            const float u0 = xiv0 - xjp[n * 3 + 0];
            const float u1 = xiv1 - xjp[n * 3 + 1];
            const float u2 = xiv2 - xjp[n * 3 + 2];
            q0_[mh] = u0 * u0;
            q1_[mh] = u1 * u1;
            q2_[mh] = u2 * u2;
        }
        float micol[8];
        #pragma unroll
        for (int j = 0; j < 8; j++) micol[j] = 0.0f;
        float pr[4] = {0.f, 0.f, 0.f, 0.f};

        #pragma unroll
        for (int nt = 0; nt < 4; nt++) {
            const int col = nt * 8 + 2 * s;
            const float4 b0 = smBaseC[col];
            const float4 b1 = smBaseC[col + 1];
            #pragma unroll
            for (int mh = 0; mh < 4; mh++) {
                const int mt = mh >> 1, hf = mh & 1;
                float va = acc[mt][nt][hf * 2 + 0] + b0.x + q0_[mh] * b0.y
                         + q1_[mh] * b0.z + q2_[mh] * b0.w;
                float vb = acc[mt][nt][hf * 2 + 1] + b1.x + q0_[mh] * b1.y
                         + q1_[mh] * b1.z + q2_[mh] * b1.w;
                const float mv0 = silu_f(va);
                const float mv1 = silu_f(vb);
                micol[nt * 2 + 0] += mv0;
                micol[nt * 2 + 1] += mv1;
                pr[mh] += mv0 * wxr_[nt * 2 + 0] + mv1 * wxr_[nt * 2 + 1];
            }
        }
        float xa0 = 0.f, xa1 = 0.f, xa2 = 0.f;
        #pragma unroll
        for (int mh = 0; mh < 4; mh++) {
            float prr = pr[mh];
            prr += __shfl_xor_sync(0xffffffffu, prr, 1);
            prr += __shfl_xor_sync(0xffffffffu, prr, 2);
            const float px = silu_f(prr + bxv);
            const int n = w * 32 + (mh >> 1) * 16 + (mh & 1) * 8 + q;
            xa0 += (xiv0 - xjp[n * 3 + 0]) * px;
            xa1 += (xiv1 - xjp[n * 3 + 1]) * px;
            xa2 += (xiv2 - xjp[n * 3 + 2]) * px;   // 4x redundant per quad
        }
        #pragma unroll
        for (int j = 0; j < 8; j++) {
            micol[j] += __shfl_xor_sync(0xffffffffu, micol[j], 4);
            micol[j] += __shfl_xor_sync(0xffffffffu, micol[j], 8);
            micol[j] += __shfl_xor_sync(0xffffffffu, micol[j], 16);
        }
        if (lane < 4) {
            #pragma unroll
            for (int nt = 0; nt < 4; nt++) {
                smMip[w * 32 + nt * 8 + 2 * lane + 0] = micol[nt * 2 + 0];
                smMip[w * 32 + nt * 8 + 2 * lane + 1] = micol[nt * 2 + 1];
            }
        }
        #pragma unroll
        for (int off = 16; off; off >>= 1) {
            xa0 += __shfl_xor_sync(0xffffffffu, xa0, off);
            xa1 += __shfl_xor_sync(0xffffffffu, xa1, off);
            xa2 += __shfl_xor_sync(0xffffffffu, xa2, off);
        }
        if (lane == 0) { smXa[w*4+0] = xa0; smXa[w*4+1] = xa1; smXa[w*4+2] = xa2; }

        // ---- barrier(2): split — warps 4-7 arrive and RUN AHEAD; w0-3 sync ----
        if (w < 4) {
            asm volatile("bar.sync 2, 256;" ::: "memory");
        } else {
            asm volatile("bar.arrive 2, 256;" ::: "memory");
        }

        // ---- tail (w0-3; warps 4-7 already in next iteration) ----
        if (w == 0) {
            float mt = 0.0f;
            #pragma unroll
            for (int wi = 0; wi < 8; wi++) mt += smMip[wi * 32 + lane];
            smMif[lane] = mt;
            float v2 = mt * __ldg(&Wx2[lane]);
            #pragma unroll
            for (int off = 16; off; off >>= 1)
                v2 += __shfl_xor_sync(0xffffffffu, v2, off);
            const float phi2 = silu_f(v2 + bx2v);
            if (lane < Cc) {
                float xt = 0.0f;
                #pragma unroll
                for (int wi = 0; wi < 8; wi++) xt += smXa[wi * 4 + lane];
                out[OUT_XI_OFF + (size_t)b * Cc + lane] =
                    smXiV[p * 4 + lane] * phi2 + xt * (1.0f / (4.0f * (float)Nn));
            }
        }
        if (w < 4) {
            asm volatile("bar.sync 1, 128;" ::: "memory");   // smMif ready (warps 0-3)
            // Wh GEMM distributed: 2 threads per output column, 48 MACs each
            const int col = tid >> 1;
            const int hf  = tid & 1;
            float a;
            if (hf == 0) {
                a = __ldg(&bh[col]);
                #pragma unroll 8
                for (int d = 0; d < 48; d++) a += smHiF[p * 64 + d] * smWh[d * Dd + col];
            } else {
                a = 0.0f;
                #pragma unroll 8
                for (int d = 48; d < 64; d++) a += smHiF[p * 64 + d] * smWh[d * Dd + col];
                #pragma unroll 8
                for (int m = 0; m < Mm; m++)  a += smMif[m] * smWh[(Dd + m) * Dd + col];
            }
            a += __shfl_xor_sync(0xffffffffu, a, 1);
            if (hf == 0) out[(size_t)b * Dd + col] = silu_f(a);
        }
        p ^= 1;
    }
    #undef STAGE_WARP
}

extern "C" void kernel_launch(void* const* d_in, const int* in_sizes, int n_in,
                              void* d_out, int out_size) {
    const float* hi  = (const float*)d_in[0];
    const float* xi  = (const float*)d_in[1];
    const float* hj  = (const float*)d_in[2];
    const float* xj  = (const float*)d_in[3];
    const float* We  = (const float*)d_in[4];
    const float* be  = (const float*)d_in[5];
    const float* Wx  = (const float*)d_in[6];
    const float* bx  = (const float*)d_in[7];
    const float* Wx2 = (const float*)d_in[8];
    const float* bx2 = (const float*)d_in[9];
    const float* Wh  = (const float*)d_in[10];
    const float* bh  = (const float*)d_in[11];
    float* out = (float*)d_out;

    cudaFuncSetAttribute(e2gn2_kernel,
                         cudaFuncAttributeMaxDynamicSharedMemorySize, SMEM_TOTAL);
    int smCount = 148;
    cudaDeviceGetAttribute(&smCount, cudaDevAttrMultiProcessorCount, 0);
    const int grid = 2 * smCount;

    e2gn2_kernel<<<grid, 256, SMEM_TOTAL>>>(hi, xi, hj, xj, We, be, Wx, bx,
                                            Wx2, bx2, Wh, bh, out);
}

// round 14
// speedup vs baseline: 1.2330x; 1.1775x over previous
#include <cuda_runtime.h>
#include <cstdint>

#define Bb 4096
#define Nn 256
#define Dd 64
#define Cc 3
#define Mm 32

#define OUT_XI_OFF ((size_t)Bb * Dd)
#define OUT_HJ_OFF (OUT_XI_OFF + (size_t)Bb * Cc)
#define OUT_XJ_OFF (OUT_HJ_OFF + (size_t)Bb * Nn * Dd)

// ---- dynamic smem layout (byte offsets) ----
#define SMO_A      0        // 256 x 64 fp32, chunk-rotated = 65536 (warp-private bands)
#define SMO_BF     65536    // B frags (tf32 RNA): 8kk x 4nt x 32 lanes x 8B = 8192
#define SMO_WH     73728    // 96 x 64 fp32 = 24576
#define SMO_XJ     98304    // 2 x 768 fp32 = 6144 (double buffered, warp-private slices)
#define SMO_HI     104448   // 3 x 64 fp32 = 768 (triple buffered)
#define SMO_BASEC  105216   // 2 x 32 x float4 = 1024 (double buffered)
#define SMO_MIP    106240   // 2 x 256 fp32 = 2048 (double buffered)
#define SMO_XA     108288   // 2 x 32 fp32 = 256 (double buffered)
#define SMO_MIF    108544   // 32 fp32 = 128
#define SMO_XIV    108672   // 3 x 4 fp32 = 48 (triple buffered)
#define SMEM_TOTAL 108720

__device__ __forceinline__ uint32_t smem_u32(const void* p) {
    uint32_t a;
    asm("{ .reg .u64 t; cvta.to.shared.u64 t, %1; cvt.u32.u64 %0, t; }" : "=r"(a) : "l"(p));
    return a;
}
__device__ __forceinline__ float silu_f(float x) {
    float e, r;
    asm("ex2.approx.f32 %0, %1;" : "=f"(e) : "f"(x * -1.442695041f));
    asm("rcp.approx.f32 %0, %1;" : "=f"(r) : "f"(e + 1.0f));
    return x * r;
}
__device__ __forceinline__ uint32_t to_tf32(float f) {
    uint32_t u;
    asm("cvt.rna.tf32.f32 %0, %1;" : "=r"(u) : "f"(f));
    return u;
}
__device__ __forceinline__ void mma_tf32(float* c, uint32_t a0, uint32_t a1,
                                         uint32_t a2, uint32_t a3,
                                         uint32_t b0, uint32_t b1) {
    asm volatile(
        "mma.sync.aligned.m16n8k8.row.col.f32.tf32.tf32.f32 "
        "{%0,%1,%2,%3}, {%4,%5,%6,%7}, {%8,%9}, {%0,%1,%2,%3};"
        : "+f"(c[0]), "+f"(c[1]), "+f"(c[2]), "+f"(c[3])
        : "r"(a0), "r"(a1), "r"(a2), "r"(a3), "r"(b0), "r"(b1));
}
__device__ __forceinline__ void stcs4(float* p, float4 v) {
    asm volatile("st.global.cs.v4.f32 [%0], {%1,%2,%3,%4};"
                 :: "l"(p), "f"(v.x), "f"(v.y), "f"(v.z), "f"(v.w) : "memory");
}
#define CP16(dst, src) asm volatile("cp.async.cg.shared.global [%0], [%1], 16;" :: "r"(dst), "l"(src))
#define CP4(dst, src)  asm volatile("cp.async.ca.shared.global [%0], [%1], 4;"  :: "r"(dst), "l"(src))
#define CPCOMMIT()     asm volatile("cp.async.commit_group;" ::: "memory")
#define CPWAIT0()      asm volatile("cp.async.wait_group 0;" ::: "memory")

__global__ __launch_bounds__(256, 2) void e2gn2_kernel(
    const float* __restrict__ hi, const float* __restrict__ xi,
    const float* __restrict__ hj, const float* __restrict__ xj,
    const float* __restrict__ We, const float* __restrict__ be,
    const float* __restrict__ Wx, const float* __restrict__ bx,
    const float* __restrict__ Wx2, const float* __restrict__ bx2,
    const float* __restrict__ Wh, const float* __restrict__ bh,
    float* __restrict__ out)
{
    extern __shared__ char sm[];

    const int tid  = threadIdx.x;
    const int w    = tid >> 5;
    const int lane = tid & 31;
    const int q    = lane >> 2;   // groupID (row in frag)
    const int s    = lane & 3;    // threadID_in_group

    float*  smWh   = (float*)(sm + SMO_WH);
    float*  smXjF  = (float*)(sm + SMO_XJ);
    float*  smHiF  = (float*)(sm + SMO_HI);
    float4* smBaseC= (float4*)(sm + SMO_BASEC);
    float*  smMip  = (float*)(sm + SMO_MIP);
    float*  smXa   = (float*)(sm + SMO_XA);
    float*  smMif  = (float*)(sm + SMO_MIF);
    float*  smXiV  = (float*)(sm + SMO_XIV);

    const uint32_t smBase = smem_u32(sm);

    // ================= one-time init =================
    for (int i = tid; i < 6144; i += 256) smWh[i] = Wh[i];
    // B frags (RNA-rounded tf32): thread holds b0=(k=kk*8+t, n=nt*8+g), b1=(k+4, n)
    for (int idx = tid; idx < 8 * 4 * 32; idx += 256) {
        const int kk = idx >> 7, rest = idx & 127;
        const int nt = rest >> 5, l2 = rest & 31;
        const int t2 = l2 & 3, g2 = l2 >> 2;
        const int k0 = kk * 8 + t2, n = nt * 8 + g2;
        uint2 bfr;
        bfr.x = to_tf32(We[(Dd + k0)     * Mm + n]);
        bfr.y = to_tf32(We[(Dd + k0 + 4) * Mm + n]);
        *(uint2*)(sm + SMO_BF + ((kk * 4 + nt) * 32 + l2) * 8) = bfr;
    }
    float wxr_[8];
    #pragma unroll
    for (int nt = 0; nt < 4; nt++) {
        wxr_[nt * 2 + 0] = Wx[nt * 8 + 2 * s + 0];
        wxr_[nt * 2 + 1] = Wx[nt * 8 + 2 * s + 1];
    }
    const float bxv  = bx[0];
    const float bx2v = bx2[0];
    __syncthreads();   // BF/WH visible before any MMA/tail

    const int bstart = blockIdx.x, bstride = gridDim.x;
    int p   = 0;   // parity for xj/mip/xa/basec
    int it3 = 0;   // hi/xiv triple-buffer slot of CURRENT block

    // ---- per-warp staging: warp w's A band + xj slice (+ w2: hi, xiv) ----
    #define STAGE_WARP(bsrc, pb, hs) do {                                          \
        const float* hjb_ = hj + (size_t)(bsrc) * Nn * Dd;                         \
        _Pragma("unroll")                                                          \
        for (int j = 0; j < 16; j++) {                                             \
            const int row_ = w * 32 + j * 2 + (lane >> 4);                         \
            const int ch_  = lane & 15;                                            \
            CP16(smBase + SMO_A + row_ * 256 + (((ch_ + row_) & 15) << 4),         \
                 hjb_ + row_ * 64 + ch_ * 4);                                      \
        }                                                                          \
        if (lane < 24) CP16(smBase + SMO_XJ + (pb) * 3072 + w * 384 + lane * 16,   \
                            xj + (size_t)(bsrc) * 768 + w * 96 + lane * 4);        \
        if (w == 2) {                                                              \
            if (lane < 16) CP16(smBase + SMO_HI + (hs) * 256 + lane * 16,          \
                                hi + (size_t)(bsrc) * 64 + lane * 4);              \
            else if (lane < 19) CP4(smBase + SMO_XIV + (hs) * 16 + (lane-16) * 4,  \
                                    xi + (size_t)(bsrc) * 3 + (lane - 16));        \
        }                                                                          \
        CPCOMMIT();                                                                \
    } while (0)

    // ---- deferred tail for block bT (w0/w1 only): parity ppT, hi-slot hsT ----
    #define DO_TAIL(bT, ppT, hsT) do {                                             \
        if (w == 0) {                                                              \
            float mt = 0.0f;                                                       \
            _Pragma("unroll")                                                      \
            for (int wi = 0; wi < 8; wi++)                                         \
                mt += smMip[(ppT) * 256 + wi * 32 + lane];                         \
            smMif[lane] = mt;                                                      \
            float v2 = mt * __ldg(&Wx2[lane]);                                     \
            _Pragma("unroll")                                                      \
            for (int off = 16; off; off >>= 1)                                     \
                v2 += __shfl_xor_sync(0xffffffffu, v2, off);                       \
            const float phi2 = silu_f(v2 + bx2v);                                  \
            if (lane < Cc) {                                                       \
                float xt = 0.0f;                                                   \
                _Pragma("unroll")                                                  \
                for (int wi = 0; wi < 8; wi++)                                     \
                    xt += smXa[(ppT) * 32 + wi * 4 + lane];                        \
                out[OUT_XI_OFF + (size_t)(bT) * Cc + lane] =                       \
                    smXiV[(hsT) * 4 + lane] * phi2 + xt * (1.0f / (4.0f * Nn));    \
            }                                                                      \
        }                                                                          \
        asm volatile("bar.sync 1, 64;" ::: "memory");                              \
        float a_ = __ldg(&bh[tid]);                                                \
        _Pragma("unroll 8")                                                        \
        for (int d = 0; d < Dd; d++)                                               \
            a_ += smHiF[(hsT) * 64 + d] * smWh[d * Dd + tid];                      \
        _Pragma("unroll 8")                                                        \
        for (int m = 0; m < Mm; m++)                                               \
            a_ += smMif[m] * smWh[(Dd + m) * Dd + tid];                            \
        out[(size_t)(bT) * Dd + tid] = silu_f(a_);                                 \
    } while (0)

    STAGE_WARP(bstart, 0, 0);   // prologue

    // ================= persistent pipelined loop =================
    for (int b = bstart; b < Bb; b += bstride) {
        const int  bn = b + bstride;
        const bool hn = bn < Bb;
        const int  nx3 = (it3 == 2) ? 0 : it3 + 1;   // slot for block bn
        const int  pv3 = (it3 == 0) ? 2 : it3 - 1;   // slot of block b-bstride

        CPWAIT0();   // per-warp: only THIS warp's band + slice must have landed

        // ---- hj + xj pass-through STG from smem (own band / slice), evict-first ----
        {
            float4* o4 = (float4*)(out + OUT_HJ_OFF + (size_t)b * Nn * Dd);
            #pragma unroll
            for (int j = 0; j < 16; j++) {
                const int row = w * 32 + j * 2 + (lane >> 4);
                const int ch  = lane & 15;
                stcs4((float*)(o4 + row * 16 + ch),
                      *(const float4*)(sm + SMO_A + row * 256 + (((ch + row) & 15) << 4)));
            }
            if (lane < 24) {
                float4* oxj = (float4*)(out + OUT_XJ_OFF + (size_t)b * 768);
                stcs4((float*)(oxj + w * 24 + lane),
                      *(const float4*)(sm + SMO_XJ + p * 3072 + w * 384 + lane * 16));
            }
        }

        // ---- MMA: own band rows [w*32, w*32+32); RNA via +0x1000 then HW truncate ----
        float acc[2][4][4];
        #pragma unroll
        for (int mt = 0; mt < 2; mt++)
            #pragma unroll
            for (int nt = 0; nt < 4; nt++)
                #pragma unroll
                for (int j = 0; j < 4; j++) acc[mt][nt][j] = 0.0f;

        #pragma unroll
        for (int mt = 0; mt < 2; mt++) {
            const int r0 = w * 32 + mt * 16 + q;
            #pragma unroll
            for (int kk = 0; kk < 8; kk++) {
                const int cA0 = (2 * kk +     q)     & 15;
                const int cA2 = (2 * kk + 1 + q)     & 15;
                const int cB0 = (2 * kk +     q + 8) & 15;
                const int cB2 = (2 * kk + 1 + q + 8) & 15;
                const uint32_t a0 = *(const uint32_t*)(sm + SMO_A + r0 * 256       + cA0 * 16 + s * 4) + 0x1000u;
                const uint32_t a1 = *(const uint32_t*)(sm + SMO_A + (r0 + 8) * 256 + cB0 * 16 + s * 4) + 0x1000u;
                const uint32_t a2 = *(const uint32_t*)(sm + SMO_A + r0 * 256       + cA2 * 16 + s * 4) + 0x1000u;
                const uint32_t a3 = *(const uint32_t*)(sm + SMO_A + (r0 + 8) * 256 + cB2 * 16 + s * 4) + 0x1000u;
                #pragma unroll
                for (int nt = 0; nt < 4; nt++) {
                    const uint2 bf = *(const uint2*)(sm + SMO_BF +
                                        ((kk * 4 + nt) * 32 + lane) * 8);
                    mma_tf32(acc[mt][nt], a0, a1, a2, a3, bf.x, bf.y);
                }
            }
        }

        // warp 2: base[m] + {base, wu0, wu1, wu2} into BaseC[p] (double buffered)
        if (w == 2) {
            float s0 = __ldg(&be[lane]), s1 = 0.f, s2 = 0.f, s3 = 0.f;
            #pragma unroll
            for (int d = 0; d < Dd; d += 4) {
                s0 += smHiF[it3 * 64 + d + 0] * __ldg(&We[(d + 0) * Mm + lane]);
                s1 += smHiF[it3 * 64 + d + 1] * __ldg(&We[(d + 1) * Mm + lane]);
                s2 += smHiF[it3 * 64 + d + 2] * __ldg(&We[(d + 2) * Mm + lane]);
                s3 += smHiF[it3 * 64 + d + 3] * __ldg(&We[(d + 3) * Mm + lane]);
            }
            smBaseC[p * 32 + lane] = make_float4((s0 + s1) + (s2 + s3),
                                        __ldg(&We[(2 * Dd + 0) * Mm + lane]),
                                        __ldg(&We[(2 * Dd + 1) * Mm + lane]),
                                        __ldg(&We[(2 * Dd + 2) * Mm + lane]));
        }

        // ---- own A band consumed: issue next block's stage immediately ----
        if (hn) STAGE_WARP(bn, p ^ 1, nx3);
        else    CPCOMMIT();   // keep group count consistent

        __syncthreads();   // barrier(1): BaseC[p] visible; orders prev epilogue's smMip

        // ---- deferred tail for previous block (w0/w1; others go straight on) ----
        if (w < 2 && b != bstart) {
            DO_TAIL(b - bstride, p ^ 1, pv3);
        }

        // ---- epilogue (block b) ----
        const float xiv0 = smXiV[it3 * 4 + 0], xiv1 = smXiV[it3 * 4 + 1],
                    xiv2 = smXiV[it3 * 4 + 2];
        const float* xjp = smXjF + p * 768;
        float q0_[4], q1_[4], q2_[4];
        #pragma unroll
        for (int mh = 0; mh < 4; mh++) {
            const int n = w * 32 + (mh >> 1) * 16 + (mh & 1) * 8 + q;
            const float u0 = xiv0 - xjp[n * 3 + 0];
            const float u1 = xiv1 - xjp[n * 3 + 1];
            const float u2 = xiv2 - xjp[n * 3 + 2];
            q0_[mh] = u0 * u0;
            q1_[mh] = u1 * u1;
            q2_[mh] = u2 * u2;
        }
        float micol[8];
        #pragma unroll
        for (int j = 0; j < 8; j++) micol[j] = 0.0f;
        float pr[4] = {0.f, 0.f, 0.f, 0.f};

        #pragma unroll
        for (int nt = 0; nt < 4; nt++) {
            const int col = nt * 8 + 2 * s;
            const float4 b0 = smBaseC[p * 32 + col];
            const float4 b1 = smBaseC[p * 32 + col + 1];
            #pragma unroll
            for (int mh = 0; mh < 4; mh++) {
                const int mt = mh >> 1, hf = mh & 1;
                float va = acc[mt][nt][hf * 2 + 0] + b0.x + q0_[mh] * b0.y
                         + q1_[mh] * b0.z + q2_[mh] * b0.w;
                float vb = acc[mt][nt][hf * 2 + 1] + b1.x + q0_[mh] * b1.y
                         + q1_[mh] * b1.z + q2_[mh] * b1.w;
                const float mv0 = silu_f(va);
                const float mv1 = silu_f(vb);
                micol[nt * 2 + 0] += mv0;
                micol[nt * 2 + 1] += mv1;
                pr[mh] += mv0 * wxr_[nt * 2 + 0] + mv1 * wxr_[nt * 2 + 1];
            }
        }
        float xa0 = 0.f, xa1 = 0.f, xa2 = 0.f;
        #pragma unroll
        for (int mh = 0; mh < 4; mh++) {
            float prr = pr[mh];
            prr += __shfl_xor_sync(0xffffffffu, prr, 1);
            prr += __shfl_xor_sync(0xffffffffu, prr, 2);
            const float px = silu_f(prr + bxv);
            const int n = w * 32 + (mh >> 1) * 16 + (mh & 1) * 8 + q;
            xa0 += (xiv0 - xjp[n * 3 + 0]) * px;
            xa1 += (xiv1 - xjp[n * 3 + 1]) * px;
            xa2 += (xiv2 - xjp[n * 3 + 2]) * px;   // 4x redundant per quad
        }
        #pragma unroll
        for (int j = 0; j < 8; j++) {
            micol[j] += __shfl_xor_sync(0xffffffffu, micol[j], 4);
            micol[j] += __shfl_xor_sync(0xffffffffu, micol[j], 8);
            micol[j] += __shfl_xor_sync(0xffffffffu, micol[j], 16);
        }
        if (lane < 4) {
            #pragma unroll
            for (int nt = 0; nt < 4; nt++) {
                smMip[p * 256 + w * 32 + nt * 8 + 2 * lane + 0] = micol[nt * 2 + 0];
                smMip[p * 256 + w * 32 + nt * 8 + 2 * lane + 1] = micol[nt * 2 + 1];
            }
        }
        #pragma unroll
        for (int off = 16; off; off >>= 1) {
            xa0 += __shfl_xor_sync(0xffffffffu, xa0, off);
            xa1 += __shfl_xor_sync(0xffffffffu, xa1, off);
            xa2 += __shfl_xor_sync(0xffffffffu, xa2, off);
        }
        if (lane == 0) {
            smXa[p * 32 + w * 4 + 0] = xa0;
            smXa[p * 32 + w * 4 + 1] = xa1;
            smXa[p * 32 + w * 4 + 2] = xa2;
        }

        p ^= 1;
        it3 = nx3;
        // no sync2: next iteration's barrier(1) orders these smMip/smXa writes
    }

    // ---- drain: tail for the final block ----
    __syncthreads();   // last epilogue's smMip/smXa visible
    if (w < 2) {
        const int bLast = bstart + ((Bb - 1 - bstart) / bstride) * bstride;
        const int pv3 = (it3 == 0) ? 2 : it3 - 1;
        DO_TAIL(bLast, p ^ 1, pv3);
    }
    #undef STAGE_WARP
    #undef DO_TAIL
}

extern "C" void kernel_launch(void* const* d_in, const int* in_sizes, int n_in,
                              void* d_out, int out_size) {
    const float* hi  = (const float*)d_in[0];
    const float* xi  = (const float*)d_in[1];
    const float* hj  = (const float*)d_in[2];
    const float* xj  = (const float*)d_in[3];
    const float* We  = (const float*)d_in[4];
    const float* be  = (const float*)d_in[5];
    const float* Wx  = (const float*)d_in[6];
    const float* bx  = (const float*)d_in[7];
    const float* Wx2 = (const float*)d_in[8];
    const float* bx2 = (const float*)d_in[9];
    const float* Wh  = (const float*)d_in[10];
    const float* bh  = (const float*)d_in[11];
    float* out = (float*)d_out;

    cudaFuncSetAttribute(e2gn2_kernel,
                         cudaFuncAttributeMaxDynamicSharedMemorySize, SMEM_TOTAL);
    int smCount = 148;
    cudaDeviceGetAttribute(&smCount, cudaDevAttrMultiProcessorCount, 0);
    const int grid = 2 * smCount;

    e2gn2_kernel<<<grid, 256, SMEM_TOTAL>>>(hi, xi, hj, xj, We, be, Wx, bx,
                                            Wx2, bx2, Wh, bh, out);
}